// round 1
// baseline (speedup 1.0000x reference)
#include <cuda_runtime.h>
#include <cuda_bf16.h>
#include <math.h>

// Problem constants
#define BATCH 4
#define SEQ   2048
#define DMODEL 1024
#define NHEAD 8
#define HDIM  128
#define MROWS (BATCH*SEQ)          // 8192
#define NTOT  (MROWS*DMODEL)       // 8388608
#define SOFTMAX_SCALE 0.03125f     // 1/sqrt(1024)

// ---------------------------------------------------------------------------
// Scratch (device globals: allocation-free rule)
// ---------------------------------------------------------------------------
__device__ float g_Qn[NTOT];
__device__ float g_Kn[NTOT];
__device__ float g_q[NTOT];
__device__ float g_k[NTOT];
__device__ float g_v[NTOT];
__device__ float g_O[NTOT];
__device__ float g_Oln[NTOT];

// ---------------------------------------------------------------------------
// LayerNorm over last dim (D=1024). One block per row, 256 threads, float4.
// ---------------------------------------------------------------------------
__global__ __launch_bounds__(256) void ln_kernel(const float* __restrict__ x,
                                                 const float* __restrict__ g,
                                                 const float* __restrict__ bta,
                                                 float* __restrict__ y)
{
    const size_t row = blockIdx.x;
    const int tid = threadIdx.x;
    float4 v = ((const float4*)(x + row * DMODEL))[tid];
    float s  = v.x + v.y + v.z + v.w;
    float ss = fmaf(v.x, v.x, fmaf(v.y, v.y, fmaf(v.z, v.z, v.w * v.w)));
#pragma unroll
    for (int o = 16; o > 0; o >>= 1) {
        s  += __shfl_xor_sync(0xffffffffu, s,  o);
        ss += __shfl_xor_sync(0xffffffffu, ss, o);
    }
    __shared__ float sb[8], ssb[8];
    if ((tid & 31) == 0) { sb[tid >> 5] = s; ssb[tid >> 5] = ss; }
    __syncthreads();
    s = 0.f; ss = 0.f;
#pragma unroll
    for (int i = 0; i < 8; i++) { s += sb[i]; ss += ssb[i]; }
    const float mean = s * (1.0f / DMODEL);
    const float var  = ss * (1.0f / DMODEL) - mean * mean;
    const float rstd = rsqrtf(var + 1e-5f);
    float4 gg = ((const float4*)g)[tid];
    float4 bb = ((const float4*)bta)[tid];
    float4 o;
    o.x = (v.x - mean) * rstd * gg.x + bb.x;
    o.y = (v.y - mean) * rstd * gg.y + bb.y;
    o.z = (v.z - mean) * rstd * gg.z + bb.z;
    o.w = (v.w - mean) * rstd * gg.w + bb.w;
    ((float4*)(y + row * DMODEL))[tid] = o;
}

// ---------------------------------------------------------------------------
// SGEMM: C[M,N] = A[M,K] @ B[K,N], row-major, 128x128 tile, 8x8 per thread.
// EPI=true: C = R + gelu_exact(A@B)  (R elementwise, same shape as C)
// M,N,K all multiples of 128 (8192/1024/1024 here).
// ---------------------------------------------------------------------------
__device__ __forceinline__ float gelu_exact(float x)
{
    return 0.5f * x * (1.0f + erff(x * 0.70710678118654752440f));
}

template <bool EPI>
__global__ __launch_bounds__(256) void sgemm(const float* __restrict__ A,
                                             const float* __restrict__ Bm,
                                             float* __restrict__ C,
                                             const float* __restrict__ R,
                                             int M, int N, int K)
{
    __shared__ float As[16][132];
    __shared__ float Bs[16][132];
    const int bx = blockIdx.x * 128;
    const int by = blockIdx.y * 128;
    const int tid = threadIdx.x;
    const int tx = tid & 15;
    const int ty = tid >> 4;

    float acc[8][8];
#pragma unroll
    for (int i = 0; i < 8; i++)
#pragma unroll
        for (int j = 0; j < 8; j++) acc[i][j] = 0.f;

    const int ar  = tid >> 1;   // 0..127 (A tile row)
    const int ac4 = tid & 1;    // A float4 col group base
    const int br  = tid >> 4;   // 0..15  (B tile row)
    const int bc4 = tid & 15;   // B float4 col

    for (int k0 = 0; k0 < K; k0 += 16) {
#pragma unroll
        for (int t = 0; t < 2; t++) {
            const int kc = (ac4 + 2 * t) * 4;
            float4 av = *(const float4*)&A[(size_t)(by + ar) * K + k0 + kc];
            As[kc + 0][ar] = av.x;
            As[kc + 1][ar] = av.y;
            As[kc + 2][ar] = av.z;
            As[kc + 3][ar] = av.w;
        }
#pragma unroll
        for (int t = 0; t < 2; t++) {
            const int nc = (bc4 + 16 * t) * 4;
            float4 bv = *(const float4*)&Bm[(size_t)(k0 + br) * N + bx + nc];
            *(float4*)&Bs[br][nc] = bv;
        }
        __syncthreads();
#pragma unroll
        for (int kk = 0; kk < 16; kk++) {
            float a[8], b[8];
            *(float4*)&a[0] = *(const float4*)&As[kk][ty * 8];
            *(float4*)&a[4] = *(const float4*)&As[kk][ty * 8 + 4];
            *(float4*)&b[0] = *(const float4*)&Bs[kk][tx * 8];
            *(float4*)&b[4] = *(const float4*)&Bs[kk][tx * 8 + 4];
#pragma unroll
            for (int i = 0; i < 8; i++)
#pragma unroll
                for (int j = 0; j < 8; j++)
                    acc[i][j] = fmaf(a[i], b[j], acc[i][j]);
        }
        __syncthreads();
    }

#pragma unroll
    for (int i = 0; i < 8; i++) {
        const size_t row = (size_t)(by + ty * 8 + i);
#pragma unroll
        for (int j = 0; j < 8; j += 4) {
            const size_t idx = row * N + bx + tx * 8 + j;
            float4 o;
            o.x = acc[i][j + 0];
            o.y = acc[i][j + 1];
            o.z = acc[i][j + 2];
            o.w = acc[i][j + 3];
            if (EPI) {
                float4 r = *(const float4*)&R[idx];
                o.x = r.x + gelu_exact(o.x);
                o.y = r.y + gelu_exact(o.y);
                o.z = r.z + gelu_exact(o.z);
                o.w = r.w + gelu_exact(o.w);
            }
            *(float4*)&C[idx] = o;
        }
    }
}

// ---------------------------------------------------------------------------
// Flash attention, fp32. BM=64 queries per block, BN=64 keys per tile, HD=128.
// Grid: (SEQ/64, BATCH*NHEAD). 256 threads as 16x16; each thread: 4 query
// rows (ty*4..+4), 4 score cols (tx*4..+4), 8 output cols (tx*8..+8).
// Q,K stored transposed in smem ([d][row], pad 65 -> conflict-free transpose
// stores, broadcast/2-way reads). P tile aliases K tile.
// smem = (128*65 + 128*65 + 64*128) * 4 = 99328 B  (2 CTAs/SM)
// ---------------------------------------------------------------------------
#define FA_SMEM_FLOATS (128 * 65 + 128 * 65 + 64 * 128)
#define FA_SMEM_BYTES  (FA_SMEM_FLOATS * 4)

__global__ __launch_bounds__(256) void flash_kernel(const float* __restrict__ qg,
                                                    const float* __restrict__ kg,
                                                    const float* __restrict__ vg,
                                                    float* __restrict__ og)
{
    extern __shared__ float sm[];
    float* Qst = sm;                 // [128][65]
    float* Kst = Qst + 128 * 65;     // [128][65]
    float* Vs  = Kst + 128 * 65;     // [64][128]
    float* Ps  = Kst;                // [64][64]  (aliases Kst; 4096 <= 8320)

    const int bh = blockIdx.y;            // b*NHEAD + h
    const int b  = bh >> 3;
    const int h  = bh & 7;
    const int m0 = blockIdx.x * 64;
    const int tid = threadIdx.x;
    const int tx = tid & 15;
    const int ty = tid >> 4;

    const size_t base = (size_t)b * SEQ * DMODEL + (size_t)h * HDIM;
    const float* qb = qg + base;
    const float* kb = kg + base;
    const float* vb = vg + base;

    // Load Q tile transposed: Qst[d][m]
    for (int idx = tid; idx < 64 * 128; idx += 256) {
        const int m = idx >> 7, d = idx & 127;
        Qst[d * 65 + m] = qb[(size_t)(m0 + m) * DMODEL + d];
    }

    float mi[4], li[4], accO[4][8];
#pragma unroll
    for (int i = 0; i < 4; i++) {
        mi[i] = -1e30f; li[i] = 0.f;
#pragma unroll
        for (int c = 0; c < 8; c++) accO[i][c] = 0.f;
    }

    for (int j0 = 0; j0 < SEQ; j0 += 64) {
        __syncthreads();   // prev tile fully consumed (also covers Q load on iter 0)
        for (int idx = tid; idx < 64 * 128; idx += 256) {
            const int n = idx >> 7, d = idx & 127;
            Kst[d * 65 + n] = kb[(size_t)(j0 + n) * DMODEL + d];
            Vs[n * 128 + d] = vb[(size_t)(j0 + n) * DMODEL + d];
        }
        __syncthreads();

        // S = Q K^T  (outer product over d)
        float s[4][4];
#pragma unroll
        for (int i = 0; i < 4; i++)
#pragma unroll
            for (int j = 0; j < 4; j++) s[i][j] = 0.f;

        for (int d = 0; d < 128; d++) {
            float a[4], bb[4];
#pragma unroll
            for (int i = 0; i < 4; i++) a[i]  = Qst[d * 65 + ty * 4 + i];
#pragma unroll
            for (int j = 0; j < 4; j++) bb[j] = Kst[d * 65 + tx * 4 + j];
#pragma unroll
            for (int i = 0; i < 4; i++)
#pragma unroll
                for (int j = 0; j < 4; j++)
                    s[i][j] = fmaf(a[i], bb[j], s[i][j]);
        }

        __syncthreads();   // everyone done reading Kst before Ps (alias) writes

        // online softmax
#pragma unroll
        for (int i = 0; i < 4; i++) {
            float mx = -1e30f;
#pragma unroll
            for (int j = 0; j < 4; j++) {
                float x = s[i][j] * SOFTMAX_SCALE;
                x = fminf(fmaxf(x, -10000.f), 10000.f);
                s[i][j] = x;
                mx = fmaxf(mx, x);
            }
#pragma unroll
            for (int o = 8; o > 0; o >>= 1)
                mx = fmaxf(mx, __shfl_xor_sync(0xffffffffu, mx, o));
            const float mnew  = fmaxf(mi[i], mx);
            const float alpha = __expf(mi[i] - mnew);
            float4 p;
            p.x = __expf(s[i][0] - mnew);
            p.y = __expf(s[i][1] - mnew);
            p.z = __expf(s[i][2] - mnew);
            p.w = __expf(s[i][3] - mnew);
            *(float4*)&Ps[(ty * 4 + i) * 64 + tx * 4] = p;
            float rs = p.x + p.y + p.z + p.w;
#pragma unroll
            for (int o = 8; o > 0; o >>= 1)
                rs += __shfl_xor_sync(0xffffffffu, rs, o);
            li[i] = li[i] * alpha + rs;
            mi[i] = mnew;
#pragma unroll
            for (int c = 0; c < 8; c++) accO[i][c] *= alpha;
        }
        __syncthreads();   // Ps visible to all

        // O += P @ V
        for (int j = 0; j < 64; j++) {
            float vv[8];
            *(float4*)&vv[0] = *(const float4*)&Vs[j * 128 + tx * 8];
            *(float4*)&vv[4] = *(const float4*)&Vs[j * 128 + tx * 8 + 4];
            float p[4];
#pragma unroll
            for (int i = 0; i < 4; i++) p[i] = Ps[(ty * 4 + i) * 64 + j];
#pragma unroll
            for (int i = 0; i < 4; i++)
#pragma unroll
                for (int c = 0; c < 8; c++)
                    accO[i][c] = fmaf(p[i], vv[c], accO[i][c]);
        }
    }

    // write O
#pragma unroll
    for (int i = 0; i < 4; i++) {
        const float inv = 1.0f / li[i];
        const size_t orow = (size_t)(b * SEQ + m0 + ty * 4 + i) * DMODEL + h * HDIM + tx * 8;
        float4 o0, o1;
        o0.x = accO[i][0] * inv; o0.y = accO[i][1] * inv;
        o0.z = accO[i][2] * inv; o0.w = accO[i][3] * inv;
        o1.x = accO[i][4] * inv; o1.y = accO[i][5] * inv;
        o1.z = accO[i][6] * inv; o1.w = accO[i][7] * inv;
        *(float4*)&og[orow]     = o0;
        *(float4*)&og[orow + 4] = o1;
    }
}

// ---------------------------------------------------------------------------
// Launch
// ---------------------------------------------------------------------------
extern "C" void kernel_launch(void* const* d_in, const int* in_sizes, int n_in,
                              void* d_out, int out_size)
{
    const float* Q     = (const float*)d_in[0];
    const float* Kin   = (const float*)d_in[1];
    const float* Vin   = (const float*)d_in[2];
    const float* Wq    = (const float*)d_in[3];
    const float* Wk    = (const float*)d_in[4];
    const float* Wv    = (const float*)d_in[5];
    const float* Wo    = (const float*)d_in[6];
    const float* pre_g = (const float*)d_in[7];
    const float* pre_b = (const float*)d_in[8];
    const float* ln_g  = (const float*)d_in[9];
    const float* ln_b  = (const float*)d_in[10];
    float* out = (float*)d_out;

    float *qn, *kn, *qq, *kk, *vv, *oo, *oln;
    cudaGetSymbolAddress((void**)&qn,  g_Qn);
    cudaGetSymbolAddress((void**)&kn,  g_Kn);
    cudaGetSymbolAddress((void**)&qq,  g_q);
    cudaGetSymbolAddress((void**)&kk,  g_k);
    cudaGetSymbolAddress((void**)&vv,  g_v);
    cudaGetSymbolAddress((void**)&oo,  g_O);
    cudaGetSymbolAddress((void**)&oln, g_Oln);

    cudaFuncSetAttribute(flash_kernel,
                         cudaFuncAttributeMaxDynamicSharedMemorySize, FA_SMEM_BYTES);

    // 1) pre-LN on Q and K
    ln_kernel<<<MROWS, 256>>>(Q,   pre_g, pre_b, qn);
    ln_kernel<<<MROWS, 256>>>(Kin, pre_g, pre_b, kn);

    // 2) projections
    dim3 gg(DMODEL / 128, MROWS / 128);
    sgemm<false><<<gg, 256>>>(qn,  Wq, qq, nullptr, MROWS, DMODEL, DMODEL);
    sgemm<false><<<gg, 256>>>(kn,  Wk, kk, nullptr, MROWS, DMODEL, DMODEL);
    sgemm<false><<<gg, 256>>>(Vin, Wv, vv, nullptr, MROWS, DMODEL, DMODEL);

    // 3) attention
    flash_kernel<<<dim3(SEQ / 64, BATCH * NHEAD), 256, FA_SMEM_BYTES>>>(qq, kk, vv, oo);

    // 4) post-LN
    ln_kernel<<<MROWS, 256>>>(oo, ln_g, ln_b, oln);

    // 5) output GEMM + gelu residual epilogue
    sgemm<true><<<gg, 256>>>(oln, Wo, out, oln, MROWS, DMODEL, DMODEL);
}

// round 2
// speedup vs baseline: 2.8768x; 2.8768x over previous
#include <cuda_runtime.h>
#include <cuda_bf16.h>
#include <math.h>
#include <stdint.h>

// Problem constants
#define BATCH 4
#define SEQ   2048
#define DMODEL 1024
#define NHEAD 8
#define HDIM  128
#define MROWS (BATCH*SEQ)          // 8192
#define NTOT  (MROWS*DMODEL)       // 8388608
#define SOFTMAX_SCALE 0.03125f     // 1/sqrt(1024)

// ---------------------------------------------------------------------------
// Scratch (device globals: allocation-free rule)
// ---------------------------------------------------------------------------
__device__ float g_Qn[NTOT];
__device__ float g_Kn[NTOT];
__device__ float g_q[NTOT];
__device__ float g_k[NTOT];
__device__ float g_v[NTOT];
__device__ float g_O[NTOT];
__device__ float g_Oln[NTOT];

// ---------------------------------------------------------------------------
// Small PTX helpers
// ---------------------------------------------------------------------------
__device__ __forceinline__ float tf32r(float x)
{
    unsigned o;
    asm("cvt.rna.tf32.f32 %0, %1;" : "=r"(o) : "f"(x));
    return __uint_as_float(o);
}

__device__ __forceinline__ void ldsm4(unsigned (&r)[4], const float* p)
{
    unsigned addr = (unsigned)__cvta_generic_to_shared(p);
    asm volatile("ldmatrix.sync.aligned.m8n8.x4.shared.b16 {%0,%1,%2,%3}, [%4];"
                 : "=r"(r[0]), "=r"(r[1]), "=r"(r[2]), "=r"(r[3]) : "r"(addr));
}

__device__ __forceinline__ void ldsm2(unsigned (&r)[2], const float* p)
{
    unsigned addr = (unsigned)__cvta_generic_to_shared(p);
    asm volatile("ldmatrix.sync.aligned.m8n8.x2.shared.b16 {%0,%1}, [%2];"
                 : "=r"(r[0]), "=r"(r[1]) : "r"(addr));
}

__device__ __forceinline__ void mma_tf32(float (&d)[4], const unsigned (&a)[4],
                                         const unsigned (&b)[2])
{
    asm volatile(
        "mma.sync.aligned.m16n8k8.row.col.f32.tf32.tf32.f32 "
        "{%0,%1,%2,%3}, {%4,%5,%6,%7}, {%8,%9}, {%0,%1,%2,%3};"
        : "+f"(d[0]), "+f"(d[1]), "+f"(d[2]), "+f"(d[3])
        : "r"(a[0]), "r"(a[1]), "r"(a[2]), "r"(a[3]), "r"(b[0]), "r"(b[1]));
}

// ---------------------------------------------------------------------------
// LayerNorm over last dim (D=1024). One block per row, 256 threads, float4.
// ---------------------------------------------------------------------------
__global__ __launch_bounds__(256) void ln_kernel(const float* __restrict__ x,
                                                 const float* __restrict__ g,
                                                 const float* __restrict__ bta,
                                                 float* __restrict__ y)
{
    const size_t row = blockIdx.x;
    const int tid = threadIdx.x;
    float4 v = ((const float4*)(x + row * DMODEL))[tid];
    float s  = v.x + v.y + v.z + v.w;
    float ss = fmaf(v.x, v.x, fmaf(v.y, v.y, fmaf(v.z, v.z, v.w * v.w)));
#pragma unroll
    for (int o = 16; o > 0; o >>= 1) {
        s  += __shfl_xor_sync(0xffffffffu, s,  o);
        ss += __shfl_xor_sync(0xffffffffu, ss, o);
    }
    __shared__ float sb[8], ssb[8];
    if ((tid & 31) == 0) { sb[tid >> 5] = s; ssb[tid >> 5] = ss; }
    __syncthreads();
    s = 0.f; ss = 0.f;
#pragma unroll
    for (int i = 0; i < 8; i++) { s += sb[i]; ss += ssb[i]; }
    const float mean = s * (1.0f / DMODEL);
    const float var  = ss * (1.0f / DMODEL) - mean * mean;
    const float rstd = rsqrtf(var + 1e-5f);
    float4 gg = ((const float4*)g)[tid];
    float4 bb = ((const float4*)bta)[tid];
    float4 o;
    o.x = (v.x - mean) * rstd * gg.x + bb.x;
    o.y = (v.y - mean) * rstd * gg.y + bb.y;
    o.z = (v.z - mean) * rstd * gg.z + bb.z;
    o.w = (v.w - mean) * rstd * gg.w + bb.w;
    ((float4*)(y + row * DMODEL))[tid] = o;
}

// ---------------------------------------------------------------------------
// TF32 tensor-core GEMM: C[M,N] = A[M,K] @ B[K,N], row-major.
// Block tile 128x128x32, 256 threads = 8 warps (2 M x 4 N), warp tile 64x32.
// A fragments via ldmatrix.x4 (tf32-in-b16 trick), B via broadcast LDS.
// EPI=true: C = R + gelu_exact(A@B)
// ---------------------------------------------------------------------------
__device__ __forceinline__ float gelu_exact(float x)
{
    return 0.5f * x * (1.0f + erff(x * 0.70710678118654752440f));
}

#define AS_STRIDE 36
#define BS_STRIDE 132

template <bool EPI>
__global__ __launch_bounds__(256) void gemm_tf32(const float* __restrict__ A,
                                                 const float* __restrict__ Bm,
                                                 float* __restrict__ C,
                                                 const float* __restrict__ R,
                                                 int M, int N, int K)
{
    __shared__ float As[128 * AS_STRIDE];
    __shared__ float Bs[32 * BS_STRIDE];

    const int tid  = threadIdx.x;
    const int lane = tid & 31;
    const int wid  = tid >> 5;
    const int grp  = lane >> 2;
    const int tig  = lane & 3;
    const int wm   = wid & 1;   // 0..1
    const int wn   = wid >> 1;  // 0..3
    const int bx   = blockIdx.x * 128;
    const int by   = blockIdx.y * 128;

    // ldmatrix.x4 per-lane source offset (rows 0..15 at k, rows 0..15 at k+4)
    const int a_row = lane & 15;
    const int a_col = (lane >> 4) << 2;

    float acc[4][4][4];
#pragma unroll
    for (int mt = 0; mt < 4; mt++)
#pragma unroll
        for (int nt = 0; nt < 4; nt++)
#pragma unroll
            for (int c = 0; c < 4; c++) acc[mt][nt][c] = 0.f;

    for (int k0 = 0; k0 < K; k0 += 32) {
        // A tile: 128x32
#pragma unroll
        for (int i = 0; i < 4; i++) {
            const int idx = tid + i * 256;
            const int r = idx >> 3, c = (idx & 7) << 2;
            float4 v = *(const float4*)&A[(size_t)(by + r) * K + k0 + c];
            float* d = &As[r * AS_STRIDE + c];
            d[0] = tf32r(v.x); d[1] = tf32r(v.y);
            d[2] = tf32r(v.z); d[3] = tf32r(v.w);
        }
        // B tile: 32x128
#pragma unroll
        for (int i = 0; i < 4; i++) {
            const int idx = tid + i * 256;
            const int r = idx >> 5, c = (idx & 31) << 2;
            float4 v = *(const float4*)&Bm[(size_t)(k0 + r) * N + bx + c];
            float* d = &Bs[r * BS_STRIDE + c];
            d[0] = tf32r(v.x); d[1] = tf32r(v.y);
            d[2] = tf32r(v.z); d[3] = tf32r(v.w);
        }
        __syncthreads();

#pragma unroll
        for (int ks = 0; ks < 4; ks++) {
            unsigned af[4][4];
#pragma unroll
            for (int mt = 0; mt < 4; mt++)
                ldsm4(af[mt], &As[(wm * 64 + mt * 16 + a_row) * AS_STRIDE + ks * 8 + a_col]);
            unsigned bf[4][2];
#pragma unroll
            for (int nt = 0; nt < 4; nt++) {
                const int nc = wn * 32 + nt * 8 + grp;
                bf[nt][0] = __float_as_uint(Bs[(ks * 8 + tig)     * BS_STRIDE + nc]);
                bf[nt][1] = __float_as_uint(Bs[(ks * 8 + tig + 4) * BS_STRIDE + nc]);
            }
#pragma unroll
            for (int mt = 0; mt < 4; mt++)
#pragma unroll
                for (int nt = 0; nt < 4; nt++)
                    mma_tf32(acc[mt][nt], af[mt], bf[nt]);
        }
        __syncthreads();
    }

    // epilogue
#pragma unroll
    for (int mt = 0; mt < 4; mt++) {
        const int r0 = by + wm * 64 + mt * 16 + grp;
#pragma unroll
        for (int nt = 0; nt < 4; nt++) {
            const int c0 = bx + wn * 32 + nt * 8 + tig * 2;
            const size_t i0 = (size_t)r0 * N + c0;
            const size_t i1 = (size_t)(r0 + 8) * N + c0;
            float2 o0 = make_float2(acc[mt][nt][0], acc[mt][nt][1]);
            float2 o1 = make_float2(acc[mt][nt][2], acc[mt][nt][3]);
            if (EPI) {
                float2 r0v = *(const float2*)&R[i0];
                float2 r1v = *(const float2*)&R[i1];
                o0.x = r0v.x + gelu_exact(o0.x);
                o0.y = r0v.y + gelu_exact(o0.y);
                o1.x = r1v.x + gelu_exact(o1.x);
                o1.y = r1v.y + gelu_exact(o1.y);
            }
            *(float2*)&C[i0] = o0;
            *(float2*)&C[i1] = o1;
        }
    }
}

// ---------------------------------------------------------------------------
// Flash attention with TF32 tensor cores.
// BM=64 q-rows per block, BN=64 keys/tile, HD=128. 256 threads = 8 warps:
// warp (wm 0..3, wn 0..1). S phase: warp tile 16x32 of S (K-dim 128).
// PV phase: warp tile 16x64 of O (K-dim 64). Row stats shared across the 2
// wn-warps via smem. P routed through smem (tf32) for ldmatrix A-frags.
// ---------------------------------------------------------------------------
#define QS_STRIDE 132
#define PS_STRIDE 68
#define FA_SMEM_FLOATS (3 * 64 * QS_STRIDE + 64 * PS_STRIDE + 256)
#define FA_SMEM_BYTES  (FA_SMEM_FLOATS * 4)

__global__ __launch_bounds__(256) void flash_tc(const float* __restrict__ qg,
                                                const float* __restrict__ kg,
                                                const float* __restrict__ vg,
                                                float* __restrict__ og)
{
    extern __shared__ float sm[];
    float* Qs   = sm;                        // [64][132]
    float* Ks   = Qs + 64 * QS_STRIDE;       // [64][132]  (rows=key, cols=d)
    float* Vs   = Ks + 64 * QS_STRIDE;       // [64][132]  (rows=key, cols=d)
    float* Ps   = Vs + 64 * QS_STRIDE;       // [64][68]
    float* redm = Ps + 64 * PS_STRIDE;       // [2][64]
    float* reds = redm + 128;                // [2][64]

    const int bh = blockIdx.y;
    const int b  = bh >> 3;
    const int h  = bh & 7;
    const int m0 = blockIdx.x * 64;
    const int tid  = threadIdx.x;
    const int lane = tid & 31;
    const int wid  = tid >> 5;
    const int grp  = lane >> 2;
    const int tig  = lane & 3;
    const int wm   = wid >> 1;   // 0..3 -> rows wm*16
    const int wn   = wid & 1;    // 0..1

    const int a_row = lane & 15;
    const int a_col = (lane >> 4) << 2;
    const int b_row = lane & 7;
    const int b_col = ((lane >> 3) & 1) << 2;

    const size_t base = (size_t)b * SEQ * DMODEL + (size_t)h * HDIM;
    const float* qb = qg + base;
    const float* kb = kg + base;
    const float* vb = vg + base;

    // Q tile 64x128 (tf32-rounded)
#pragma unroll
    for (int i = 0; i < 8; i++) {
        const int idx = tid + i * 256;
        const int r = idx >> 5, c = (idx & 31) << 2;
        float4 v = *(const float4*)&qb[(size_t)(m0 + r) * DMODEL + c];
        float* d = &Qs[r * QS_STRIDE + c];
        d[0] = tf32r(v.x); d[1] = tf32r(v.y);
        d[2] = tf32r(v.z); d[3] = tf32r(v.w);
    }

    float mi[2] = {-1e30f, -1e30f};
    float li[2] = {0.f, 0.f};
    float oacc[8][4];
#pragma unroll
    for (int nt = 0; nt < 8; nt++)
#pragma unroll
        for (int c = 0; c < 4; c++) oacc[nt][c] = 0.f;

    const int rrow0 = wm * 16 + grp;

    for (int j0 = 0; j0 < SEQ; j0 += 64) {
        __syncthreads();   // prev tile fully consumed
#pragma unroll
        for (int i = 0; i < 8; i++) {
            const int idx = tid + i * 256;
            const int r = idx >> 5, c = (idx & 31) << 2;
            float4 kv = *(const float4*)&kb[(size_t)(j0 + r) * DMODEL + c];
            float4 vv = *(const float4*)&vb[(size_t)(j0 + r) * DMODEL + c];
            float* dk = &Ks[r * QS_STRIDE + c];
            float* dv = &Vs[r * QS_STRIDE + c];
            dk[0] = tf32r(kv.x); dk[1] = tf32r(kv.y);
            dk[2] = tf32r(kv.z); dk[3] = tf32r(kv.w);
            dv[0] = tf32r(vv.x); dv[1] = tf32r(vv.y);
            dv[2] = tf32r(vv.z); dv[3] = tf32r(vv.w);
        }
        __syncthreads();

        // ---- S = Q K^T : warp tile 16x32, K-dim 128 ----
        float s[4][4];
#pragma unroll
        for (int nt = 0; nt < 4; nt++)
#pragma unroll
            for (int c = 0; c < 4; c++) s[nt][c] = 0.f;

#pragma unroll
        for (int ks = 0; ks < 16; ks++) {
            unsigned af[4];
            ldsm4(af, &Qs[(wm * 16 + a_row) * QS_STRIDE + ks * 8 + a_col]);
#pragma unroll
            for (int nt = 0; nt < 4; nt++) {
                unsigned bf[2];
                ldsm2(bf, &Ks[(wn * 32 + nt * 8 + b_row) * QS_STRIDE + ks * 8 + b_col]);
                mma_tf32(s[nt], af, bf);
            }
        }

        // ---- online softmax ----
        float mx0 = -1e30f, mx1 = -1e30f;
#pragma unroll
        for (int nt = 0; nt < 4; nt++) {
#pragma unroll
            for (int c = 0; c < 4; c++) {
                float x = s[nt][c] * SOFTMAX_SCALE;
                x = fminf(fmaxf(x, -10000.f), 10000.f);
                s[nt][c] = x;
            }
            mx0 = fmaxf(mx0, fmaxf(s[nt][0], s[nt][1]));
            mx1 = fmaxf(mx1, fmaxf(s[nt][2], s[nt][3]));
        }
        mx0 = fmaxf(mx0, __shfl_xor_sync(0xffffffffu, mx0, 1));
        mx0 = fmaxf(mx0, __shfl_xor_sync(0xffffffffu, mx0, 2));
        mx1 = fmaxf(mx1, __shfl_xor_sync(0xffffffffu, mx1, 1));
        mx1 = fmaxf(mx1, __shfl_xor_sync(0xffffffffu, mx1, 2));
        if (tig == 0) {
            redm[wn * 64 + rrow0]     = mx0;
            redm[wn * 64 + rrow0 + 8] = mx1;
        }
        __syncthreads();
        const float om0 = redm[(1 - wn) * 64 + rrow0];
        const float om1 = redm[(1 - wn) * 64 + rrow0 + 8];
        const float mn0 = fmaxf(mi[0], fmaxf(mx0, om0));
        const float mn1 = fmaxf(mi[1], fmaxf(mx1, om1));
        const float al0 = __expf(mi[0] - mn0);
        const float al1 = __expf(mi[1] - mn1);
        mi[0] = mn0; mi[1] = mn1;

        float sum0 = 0.f, sum1 = 0.f;
#pragma unroll
        for (int nt = 0; nt < 4; nt++) {
            const float p0 = __expf(s[nt][0] - mn0);
            const float p1 = __expf(s[nt][1] - mn0);
            const float p2 = __expf(s[nt][2] - mn1);
            const float p3 = __expf(s[nt][3] - mn1);
            sum0 += p0 + p1;
            sum1 += p2 + p3;
            const int col = wn * 32 + nt * 8 + tig * 2;
            *(float2*)&Ps[(rrow0)     * PS_STRIDE + col] = make_float2(tf32r(p0), tf32r(p1));
            *(float2*)&Ps[(rrow0 + 8) * PS_STRIDE + col] = make_float2(tf32r(p2), tf32r(p3));
        }
        sum0 += __shfl_xor_sync(0xffffffffu, sum0, 1);
        sum0 += __shfl_xor_sync(0xffffffffu, sum0, 2);
        sum1 += __shfl_xor_sync(0xffffffffu, sum1, 1);
        sum1 += __shfl_xor_sync(0xffffffffu, sum1, 2);
        if (tig == 0) {
            reds[wn * 64 + rrow0]     = sum0;
            reds[wn * 64 + rrow0 + 8] = sum1;
        }
        // rescale O while the exchange lands
#pragma unroll
        for (int nt = 0; nt < 8; nt++) {
            oacc[nt][0] *= al0; oacc[nt][1] *= al0;
            oacc[nt][2] *= al1; oacc[nt][3] *= al1;
        }
        __syncthreads();
        li[0] = li[0] * al0 + sum0 + reds[(1 - wn) * 64 + rrow0];
        li[1] = li[1] * al1 + sum1 + reds[(1 - wn) * 64 + rrow0 + 8];

        // ---- O += P V : warp tile 16x64, K-dim 64 ----
#pragma unroll
        for (int ks = 0; ks < 8; ks++) {
            unsigned af[4];
            ldsm4(af, &Ps[(wm * 16 + a_row) * PS_STRIDE + ks * 8 + a_col]);
#pragma unroll
            for (int nt = 0; nt < 8; nt++) {
                const int nc = wn * 64 + nt * 8 + grp;
                unsigned bf[2];
                bf[0] = __float_as_uint(Vs[(ks * 8 + tig)     * QS_STRIDE + nc]);
                bf[1] = __float_as_uint(Vs[(ks * 8 + tig + 4) * QS_STRIDE + nc]);
                mma_tf32(oacc[nt], af, bf);
            }
        }
    }

    // write O
    const float i0 = 1.0f / li[0];
    const float i1 = 1.0f / li[1];
    const size_t row0 = (size_t)(b * SEQ + m0 + wm * 16 + grp);
#pragma unroll
    for (int nt = 0; nt < 8; nt++) {
        const int col = h * HDIM + wn * 64 + nt * 8 + tig * 2;
        *(float2*)&og[row0 * DMODEL + col]       = make_float2(oacc[nt][0] * i0, oacc[nt][1] * i0);
        *(float2*)&og[(row0 + 8) * DMODEL + col] = make_float2(oacc[nt][2] * i1, oacc[nt][3] * i1);
    }
}

// ---------------------------------------------------------------------------
// Launch
// ---------------------------------------------------------------------------
extern "C" void kernel_launch(void* const* d_in, const int* in_sizes, int n_in,
                              void* d_out, int out_size)
{
    const float* Q     = (const float*)d_in[0];
    const float* Kin   = (const float*)d_in[1];
    const float* Vin   = (const float*)d_in[2];
    const float* Wq    = (const float*)d_in[3];
    const float* Wk    = (const float*)d_in[4];
    const float* Wv    = (const float*)d_in[5];
    const float* Wo    = (const float*)d_in[6];
    const float* pre_g = (const float*)d_in[7];
    const float* pre_b = (const float*)d_in[8];
    const float* ln_g  = (const float*)d_in[9];
    const float* ln_b  = (const float*)d_in[10];
    float* out = (float*)d_out;

    float *qn, *kn, *qq, *kk, *vv, *oo, *oln;
    cudaGetSymbolAddress((void**)&qn,  g_Qn);
    cudaGetSymbolAddress((void**)&kn,  g_Kn);
    cudaGetSymbolAddress((void**)&qq,  g_q);
    cudaGetSymbolAddress((void**)&kk,  g_k);
    cudaGetSymbolAddress((void**)&vv,  g_v);
    cudaGetSymbolAddress((void**)&oo,  g_O);
    cudaGetSymbolAddress((void**)&oln, g_Oln);

    cudaFuncSetAttribute(flash_tc,
                         cudaFuncAttributeMaxDynamicSharedMemorySize, FA_SMEM_BYTES);

    // 1) pre-LN on Q and K
    ln_kernel<<<MROWS, 256>>>(Q,   pre_g, pre_b, qn);
    ln_kernel<<<MROWS, 256>>>(Kin, pre_g, pre_b, kn);

    // 2) projections (TF32 tensor cores)
    dim3 gg(DMODEL / 128, MROWS / 128);
    gemm_tf32<false><<<gg, 256>>>(qn,  Wq, qq, nullptr, MROWS, DMODEL, DMODEL);
    gemm_tf32<false><<<gg, 256>>>(kn,  Wk, kk, nullptr, MROWS, DMODEL, DMODEL);
    gemm_tf32<false><<<gg, 256>>>(Vin, Wv, vv, nullptr, MROWS, DMODEL, DMODEL);

    // 3) attention (TF32 tensor cores)
    flash_tc<<<dim3(SEQ / 64, BATCH * NHEAD), 256, FA_SMEM_BYTES>>>(qq, kk, vv, oo);

    // 4) post-LN
    ln_kernel<<<MROWS, 256>>>(oo, ln_g, ln_b, oln);

    // 5) output GEMM + gelu residual epilogue
    gemm_tf32<true><<<gg, 256>>>(oln, Wo, out, oln, MROWS, DMODEL, DMODEL);
}

// round 3
// speedup vs baseline: 4.0073x; 1.3930x over previous
#include <cuda_runtime.h>
#include <cuda_bf16.h>
#include <math.h>
#include <stdint.h>

// Problem constants
#define BATCH 4
#define SEQ   2048
#define DMODEL 1024
#define NHEAD 8
#define HDIM  128
#define MROWS (BATCH*SEQ)          // 8192
#define NTOT  (MROWS*DMODEL)       // 8388608
#define SOFTMAX_SCALE 0.03125f     // 1/sqrt(1024)

// ---------------------------------------------------------------------------
// Scratch (device globals: allocation-free rule)
// ---------------------------------------------------------------------------
__device__ float g_Qn[NTOT];      // LN(Q) tf32-rounded
__device__ float g_Kn[NTOT];      // LN(K) tf32-rounded
__device__ float g_Vr[NTOT];      // V input tf32-rounded
__device__ float g_q[NTOT];       // q projection (tf32-rounded)
__device__ float g_k[NTOT];       // k projection (tf32-rounded)
__device__ float g_v[NTOT];       // v projection (tf32-rounded)
__device__ float g_O[NTOT];       // attention out (fp32)
__device__ float g_OlnR[NTOT];    // post-LN tf32-rounded (GEMM A)
__device__ float g_OlnF[NTOT];    // post-LN full fp32 (residual)
__device__ float g_Wr[4 * DMODEL * DMODEL];  // rounded weights

// ---------------------------------------------------------------------------
// PTX helpers
// ---------------------------------------------------------------------------
__device__ __forceinline__ float tf32r(float x)
{
    unsigned o;
    asm("cvt.rna.tf32.f32 %0, %1;" : "=r"(o) : "f"(x));
    return __uint_as_float(o);
}

__device__ __forceinline__ void cpa16(float* dst, const float* src)
{
    unsigned d = (unsigned)__cvta_generic_to_shared(dst);
    asm volatile("cp.async.ca.shared.global [%0], [%1], 16;" :: "r"(d), "l"(src));
}
#define CP_COMMIT() asm volatile("cp.async.commit_group;")
#define CP_WAIT0()  asm volatile("cp.async.wait_group 0;")
#define CP_WAIT1()  asm volatile("cp.async.wait_group 1;")

__device__ __forceinline__ void ldsm4(unsigned (&r)[4], const float* p)
{
    unsigned addr = (unsigned)__cvta_generic_to_shared(p);
    asm volatile("ldmatrix.sync.aligned.m8n8.x4.shared.b16 {%0,%1,%2,%3}, [%4];"
                 : "=r"(r[0]), "=r"(r[1]), "=r"(r[2]), "=r"(r[3]) : "r"(addr));
}

__device__ __forceinline__ void ldsm2(unsigned (&r)[2], const float* p)
{
    unsigned addr = (unsigned)__cvta_generic_to_shared(p);
    asm volatile("ldmatrix.sync.aligned.m8n8.x2.shared.b16 {%0,%1}, [%2];"
                 : "=r"(r[0]), "=r"(r[1]) : "r"(addr));
}

__device__ __forceinline__ void mma_tf32(float (&d)[4], const unsigned (&a)[4],
                                         const unsigned (&b)[2])
{
    asm volatile(
        "mma.sync.aligned.m16n8k8.row.col.f32.tf32.tf32.f32 "
        "{%0,%1,%2,%3}, {%4,%5,%6,%7}, {%8,%9}, {%0,%1,%2,%3};"
        : "+f"(d[0]), "+f"(d[1]), "+f"(d[2]), "+f"(d[3])
        : "r"(a[0]), "r"(a[1]), "r"(a[2]), "r"(a[3]), "r"(b[0]), "r"(b[1]));
}

// ---------------------------------------------------------------------------
// Elementwise tf32 rounding (weights, V input)
// ---------------------------------------------------------------------------
__global__ __launch_bounds__(256) void round_tf32(const float* __restrict__ x,
                                                  float* __restrict__ y, int n4)
{
    const int i = blockIdx.x * 256 + threadIdx.x;
    if (i < n4) {
        float4 v = ((const float4*)x)[i];
        float4 o;
        o.x = tf32r(v.x); o.y = tf32r(v.y);
        o.z = tf32r(v.z); o.w = tf32r(v.w);
        ((float4*)y)[i] = o;
    }
}

// ---------------------------------------------------------------------------
// LayerNorm over last dim (D=1024). y = tf32-rounded; y2 (DUAL) = full fp32.
// ---------------------------------------------------------------------------
template <bool DUAL>
__global__ __launch_bounds__(256) void ln_kernel(const float* __restrict__ x,
                                                 const float* __restrict__ g,
                                                 const float* __restrict__ bta,
                                                 float* __restrict__ y,
                                                 float* __restrict__ y2)
{
    const size_t row = blockIdx.x;
    const int tid = threadIdx.x;
    float4 v = ((const float4*)(x + row * DMODEL))[tid];
    float s  = v.x + v.y + v.z + v.w;
    float ss = fmaf(v.x, v.x, fmaf(v.y, v.y, fmaf(v.z, v.z, v.w * v.w)));
#pragma unroll
    for (int o = 16; o > 0; o >>= 1) {
        s  += __shfl_xor_sync(0xffffffffu, s,  o);
        ss += __shfl_xor_sync(0xffffffffu, ss, o);
    }
    __shared__ float sb[8], ssb[8];
    if ((tid & 31) == 0) { sb[tid >> 5] = s; ssb[tid >> 5] = ss; }
    __syncthreads();
    s = 0.f; ss = 0.f;
#pragma unroll
    for (int i = 0; i < 8; i++) { s += sb[i]; ss += ssb[i]; }
    const float mean = s * (1.0f / DMODEL);
    const float var  = ss * (1.0f / DMODEL) - mean * mean;
    const float rstd = rsqrtf(var + 1e-5f);
    float4 gg = ((const float4*)g)[tid];
    float4 bb = ((const float4*)bta)[tid];
    float4 o;
    o.x = (v.x - mean) * rstd * gg.x + bb.x;
    o.y = (v.y - mean) * rstd * gg.y + bb.y;
    o.z = (v.z - mean) * rstd * gg.z + bb.z;
    o.w = (v.w - mean) * rstd * gg.w + bb.w;
    if (DUAL) ((float4*)(y2 + row * DMODEL))[tid] = o;
    float4 r;
    r.x = tf32r(o.x); r.y = tf32r(o.y); r.z = tf32r(o.z); r.w = tf32r(o.w);
    ((float4*)(y + row * DMODEL))[tid] = r;
}

// ---------------------------------------------------------------------------
// TF32 GEMM: C[M,N] = A[M,K] @ B[K,N], inputs pre-rounded to tf32.
// 128x128x32 tile, 8 warps (2M x 4N), warp 64x32. cp.async double-buffered.
// EPI: C = R + gelu_exact(A@B).  ROUND: C tf32-rounded on store.
// ---------------------------------------------------------------------------
__device__ __forceinline__ float gelu_exact(float x)
{
    return 0.5f * x * (1.0f + erff(x * 0.70710678118654752440f));
}

#define AS_STRIDE 36    // 4 mod 32 -> ldmatrix conflict-free
#define BS_STRIDE 136   // 8 mod 32 -> scalar B-frag loads conflict-free
#define G_ABUF (128 * AS_STRIDE)   // 4608 floats
#define G_BBUF (32 * BS_STRIDE)    // 4352 floats
#define G_SMEM_FLOATS (2 * G_ABUF + 2 * G_BBUF)
#define G_SMEM_BYTES  (G_SMEM_FLOATS * 4)   // 71680

template <bool EPI, bool ROUND>
__global__ __launch_bounds__(256, 2) void gemm_tf32(const float* __restrict__ A,
                                                    const float* __restrict__ Bm,
                                                    float* __restrict__ C,
                                                    const float* __restrict__ R,
                                                    int M, int N, int K)
{
    extern __shared__ float sm[];
    float* As = sm;                  // [2][128][36]
    float* Bs = sm + 2 * G_ABUF;     // [2][32][136]

    const int tid  = threadIdx.x;
    const int lane = tid & 31;
    const int wid  = tid >> 5;
    const int grp  = lane >> 2;
    const int tig  = lane & 3;
    const int wm   = wid & 1;
    const int wn   = wid >> 1;
    const int bx   = blockIdx.x * 128;
    const int by   = blockIdx.y * 128;

    const int a_row = lane & 15;
    const int a_col = (lane >> 4) << 2;

    // per-thread load coords
    const int lar = tid >> 3;           // A row 0..31 step... (idx>>3 over 1024)
    const int lac = (tid & 7) << 2;     // A col
    const int lbr = tid >> 5;           // B row (k)
    const int lbc = (tid & 31) << 2;    // B col (n)

    float acc[4][4][4];
#pragma unroll
    for (int mt = 0; mt < 4; mt++)
#pragma unroll
        for (int nt = 0; nt < 4; nt++)
#pragma unroll
            for (int c = 0; c < 4; c++) acc[mt][nt][c] = 0.f;

    const int nk = K >> 5;

    // prologue: tile 0
    {
#pragma unroll
        for (int i = 0; i < 4; i++) {
            const int r = lar + i * 32;
            cpa16(&As[r * AS_STRIDE + lac], &A[(size_t)(by + r) * K + lac]);
        }
#pragma unroll
        for (int i = 0; i < 4; i++) {
            const int r = lbr + i * 8;
            cpa16(&Bs[r * BS_STRIDE + lbc], &Bm[(size_t)r * N + bx + lbc]);
        }
        CP_COMMIT();
    }

    for (int t = 0; t < nk; t++) {
        const int cur = t & 1;
        if (t + 1 < nk) {
            const int nxt = cur ^ 1;
            const int k0 = (t + 1) << 5;
#pragma unroll
            for (int i = 0; i < 4; i++) {
                const int r = lar + i * 32;
                cpa16(&As[nxt * G_ABUF + r * AS_STRIDE + lac],
                      &A[(size_t)(by + r) * K + k0 + lac]);
            }
#pragma unroll
            for (int i = 0; i < 4; i++) {
                const int r = lbr + i * 8;
                cpa16(&Bs[nxt * G_BBUF + r * BS_STRIDE + lbc],
                      &Bm[(size_t)(k0 + r) * N + bx + lbc]);
            }
            CP_COMMIT();
            CP_WAIT1();
        } else {
            CP_WAIT0();
        }
        __syncthreads();

        const float* Ab = As + cur * G_ABUF;
        const float* Bb = Bs + cur * G_BBUF;
#pragma unroll
        for (int ks = 0; ks < 4; ks++) {
            unsigned af[4][4];
#pragma unroll
            for (int mt = 0; mt < 4; mt++)
                ldsm4(af[mt], &Ab[(wm * 64 + mt * 16 + a_row) * AS_STRIDE + ks * 8 + a_col]);
            unsigned bf[4][2];
#pragma unroll
            for (int nt = 0; nt < 4; nt++) {
                const int nc = wn * 32 + nt * 8 + grp;
                bf[nt][0] = __float_as_uint(Bb[(ks * 8 + tig)     * BS_STRIDE + nc]);
                bf[nt][1] = __float_as_uint(Bb[(ks * 8 + tig + 4) * BS_STRIDE + nc]);
            }
#pragma unroll
            for (int mt = 0; mt < 4; mt++)
#pragma unroll
                for (int nt = 0; nt < 4; nt++)
                    mma_tf32(acc[mt][nt], af[mt], bf[nt]);
        }
        __syncthreads();
    }

    // epilogue
#pragma unroll
    for (int mt = 0; mt < 4; mt++) {
        const int r0 = by + wm * 64 + mt * 16 + grp;
#pragma unroll
        for (int nt = 0; nt < 4; nt++) {
            const int c0 = bx + wn * 32 + nt * 8 + tig * 2;
            const size_t i0 = (size_t)r0 * N + c0;
            const size_t i1 = (size_t)(r0 + 8) * N + c0;
            float2 o0 = make_float2(acc[mt][nt][0], acc[mt][nt][1]);
            float2 o1 = make_float2(acc[mt][nt][2], acc[mt][nt][3]);
            if (EPI) {
                float2 r0v = *(const float2*)&R[i0];
                float2 r1v = *(const float2*)&R[i1];
                o0.x = r0v.x + gelu_exact(o0.x);
                o0.y = r0v.y + gelu_exact(o0.y);
                o1.x = r1v.x + gelu_exact(o1.x);
                o1.y = r1v.y + gelu_exact(o1.y);
            }
            if (ROUND) {
                o0.x = tf32r(o0.x); o0.y = tf32r(o0.y);
                o1.x = tf32r(o1.x); o1.y = tf32r(o1.y);
            }
            *(float2*)&C[i0] = o0;
            *(float2*)&C[i1] = o1;
        }
    }
}

// ---------------------------------------------------------------------------
// Flash attention, TF32 tensor cores. BM=128, BN=64, HD=128.
// 8 warps; warp w owns rows w*16..w*16+15 fully -> warp-local softmax,
// warp-private P strip (no block syncs for softmax). Inputs pre-rounded.
// ---------------------------------------------------------------------------
#define FA_QS 132
#define FA_KS 132
#define FA_VS 136
#define FA_PS 68
#define FA_Q_OFF 0
#define FA_K_OFF (128 * FA_QS)
#define FA_V_OFF (FA_K_OFF + 64 * FA_KS)
#define FA_P_OFF (FA_V_OFF + 64 * FA_VS)
#define FA_SMEM_FLOATS (FA_P_OFF + 128 * FA_PS)
#define FA_SMEM_BYTES  (FA_SMEM_FLOATS * 4)   // 171008

__global__ __launch_bounds__(256, 1) void flash_tc(const float* __restrict__ qg,
                                                   const float* __restrict__ kg,
                                                   const float* __restrict__ vg,
                                                   float* __restrict__ og)
{
    extern __shared__ float sm[];
    float* Qs = sm + FA_Q_OFF;   // [128][132]
    float* Ks = sm + FA_K_OFF;   // [64][132]
    float* Vs = sm + FA_V_OFF;   // [64][136]
    float* Ps = sm + FA_P_OFF;   // [128][68]

    const int bh = blockIdx.y;
    const int b  = bh >> 3;
    const int h  = bh & 7;
    const int m0 = blockIdx.x * 128;
    const int tid  = threadIdx.x;
    const int lane = tid & 31;
    const int wid  = tid >> 5;          // 0..7 -> rows wid*16
    const int grp  = lane >> 2;
    const int tig  = lane & 3;

    const int a_row = lane & 15;
    const int a_col = (lane >> 4) << 2;
    const int b_row = lane & 7;
    const int b_col = ((lane >> 3) & 1) << 2;

    const size_t base = (size_t)b * SEQ * DMODEL + (size_t)h * HDIM;
    const float* qb = qg + base;
    const float* kb = kg + base;
    const float* vb = vg + base;

    // Q tile 128x128 via cp.async
    {
        const int r = tid >> 5;
        const int c = (tid & 31) << 2;
#pragma unroll
        for (int i = 0; i < 16; i++)
            cpa16(&Qs[(r + i * 8) * FA_QS + c], &qb[(size_t)(m0 + r + i * 8) * DMODEL + c]);
        CP_COMMIT();
    }

    float mi[2] = {-1e30f, -1e30f};
    float li[2] = {0.f, 0.f};
    float oacc[16][4];
#pragma unroll
    for (int nt = 0; nt < 16; nt++)
#pragma unroll
        for (int c = 0; c < 4; c++) oacc[nt][c] = 0.f;

    const int ldr = tid >> 5;            // K/V load row base
    const int ldc = (tid & 31) << 2;

    for (int j0 = 0; j0 < SEQ; j0 += 64) {
        __syncthreads();   // prev K/V fully consumed
#pragma unroll
        for (int i = 0; i < 8; i++) {
            const int r = ldr + i * 8;
            cpa16(&Ks[r * FA_KS + ldc], &kb[(size_t)(j0 + r) * DMODEL + ldc]);
            cpa16(&Vs[r * FA_VS + ldc], &vb[(size_t)(j0 + r) * DMODEL + ldc]);
        }
        CP_COMMIT();
        CP_WAIT0();
        __syncthreads();

        // ---- S = Q K^T : warp tile 16x64, K-dim 128 ----
        float s[8][4];
#pragma unroll
        for (int nt = 0; nt < 8; nt++)
#pragma unroll
            for (int c = 0; c < 4; c++) s[nt][c] = 0.f;

#pragma unroll
        for (int ks = 0; ks < 16; ks++) {
            unsigned af[4];
            ldsm4(af, &Qs[(wid * 16 + a_row) * FA_QS + ks * 8 + a_col]);
#pragma unroll
            for (int nt = 0; nt < 8; nt++) {
                unsigned bf[2];
                ldsm2(bf, &Ks[(nt * 8 + b_row) * FA_KS + ks * 8 + b_col]);
                mma_tf32(s[nt], af, bf);
            }
        }

        // ---- warp-local online softmax (rows grp, grp+8 of warp strip) ----
        float mx0 = -1e30f, mx1 = -1e30f;
#pragma unroll
        for (int nt = 0; nt < 8; nt++) {
#pragma unroll
            for (int c = 0; c < 4; c++) {
                float x = s[nt][c] * SOFTMAX_SCALE;
                x = fminf(fmaxf(x, -10000.f), 10000.f);
                s[nt][c] = x;
            }
            mx0 = fmaxf(mx0, fmaxf(s[nt][0], s[nt][1]));
            mx1 = fmaxf(mx1, fmaxf(s[nt][2], s[nt][3]));
        }
        mx0 = fmaxf(mx0, __shfl_xor_sync(0xffffffffu, mx0, 1));
        mx0 = fmaxf(mx0, __shfl_xor_sync(0xffffffffu, mx0, 2));
        mx1 = fmaxf(mx1, __shfl_xor_sync(0xffffffffu, mx1, 1));
        mx1 = fmaxf(mx1, __shfl_xor_sync(0xffffffffu, mx1, 2));
        const float mn0 = fmaxf(mi[0], mx0);
        const float mn1 = fmaxf(mi[1], mx1);
        const float al0 = __expf(mi[0] - mn0);
        const float al1 = __expf(mi[1] - mn1);
        mi[0] = mn0; mi[1] = mn1;

        float sum0 = 0.f, sum1 = 0.f;
        const int prow = wid * 16 + grp;
#pragma unroll
        for (int nt = 0; nt < 8; nt++) {
            const float p0 = __expf(s[nt][0] - mn0);
            const float p1 = __expf(s[nt][1] - mn0);
            const float p2 = __expf(s[nt][2] - mn1);
            const float p3 = __expf(s[nt][3] - mn1);
            sum0 += p0 + p1;
            sum1 += p2 + p3;
            const int col = nt * 8 + tig * 2;
            *(float2*)&Ps[prow * FA_PS + col]       = make_float2(tf32r(p0), tf32r(p1));
            *(float2*)&Ps[(prow + 8) * FA_PS + col] = make_float2(tf32r(p2), tf32r(p3));
        }
        sum0 += __shfl_xor_sync(0xffffffffu, sum0, 1);
        sum0 += __shfl_xor_sync(0xffffffffu, sum0, 2);
        sum1 += __shfl_xor_sync(0xffffffffu, sum1, 1);
        sum1 += __shfl_xor_sync(0xffffffffu, sum1, 2);
        li[0] = li[0] * al0 + sum0;
        li[1] = li[1] * al1 + sum1;

        // rescale O
#pragma unroll
        for (int nt = 0; nt < 16; nt++) {
            oacc[nt][0] *= al0; oacc[nt][1] *= al0;
            oacc[nt][2] *= al1; oacc[nt][3] *= al1;
        }
        __syncwarp();   // P strip visible within warp

        // ---- O += P V : warp tile 16x128, K-dim 64 ----
#pragma unroll
        for (int ks = 0; ks < 8; ks++) {
            unsigned af[4];
            ldsm4(af, &Ps[(wid * 16 + a_row) * FA_PS + ks * 8 + a_col]);
#pragma unroll
            for (int nt = 0; nt < 16; nt++) {
                unsigned bf[2];
                const int nc = nt * 8 + grp;
                bf[0] = __float_as_uint(Vs[(ks * 8 + tig)     * FA_VS + nc]);
                bf[1] = __float_as_uint(Vs[(ks * 8 + tig + 4) * FA_VS + nc]);
                mma_tf32(oacc[nt], af, bf);
            }
        }
        __syncwarp();   // P reads done before next tile's softmax rewrites
    }

    // write O
    const float i0 = 1.0f / li[0];
    const float i1 = 1.0f / li[1];
    const size_t row0 = (size_t)(b * SEQ + m0 + wid * 16 + grp);
#pragma unroll
    for (int nt = 0; nt < 16; nt++) {
        const int col = h * HDIM + nt * 8 + tig * 2;
        *(float2*)&og[row0 * DMODEL + col]       = make_float2(oacc[nt][0] * i0, oacc[nt][1] * i0);
        *(float2*)&og[(row0 + 8) * DMODEL + col] = make_float2(oacc[nt][2] * i1, oacc[nt][3] * i1);
    }
}

// ---------------------------------------------------------------------------
// Launch
// ---------------------------------------------------------------------------
extern "C" void kernel_launch(void* const* d_in, const int* in_sizes, int n_in,
                              void* d_out, int out_size)
{
    const float* Q     = (const float*)d_in[0];
    const float* Kin   = (const float*)d_in[1];
    const float* Vin   = (const float*)d_in[2];
    const float* Wq    = (const float*)d_in[3];
    const float* Wk    = (const float*)d_in[4];
    const float* Wv    = (const float*)d_in[5];
    const float* Wo    = (const float*)d_in[6];
    const float* pre_g = (const float*)d_in[7];
    const float* pre_b = (const float*)d_in[8];
    const float* ln_g  = (const float*)d_in[9];
    const float* ln_b  = (const float*)d_in[10];
    float* out = (float*)d_out;

    float *qn, *kn, *vr, *qq, *kk, *vv, *oo, *olnR, *olnF, *wr;
    cudaGetSymbolAddress((void**)&qn,   g_Qn);
    cudaGetSymbolAddress((void**)&kn,   g_Kn);
    cudaGetSymbolAddress((void**)&vr,   g_Vr);
    cudaGetSymbolAddress((void**)&qq,   g_q);
    cudaGetSymbolAddress((void**)&kk,   g_k);
    cudaGetSymbolAddress((void**)&vv,   g_v);
    cudaGetSymbolAddress((void**)&oo,   g_O);
    cudaGetSymbolAddress((void**)&olnR, g_OlnR);
    cudaGetSymbolAddress((void**)&olnF, g_OlnF);
    cudaGetSymbolAddress((void**)&wr,   g_Wr);

    cudaFuncSetAttribute(flash_tc,
                         cudaFuncAttributeMaxDynamicSharedMemorySize, FA_SMEM_BYTES);
    cudaFuncSetAttribute(gemm_tf32<false, true>,
                         cudaFuncAttributeMaxDynamicSharedMemorySize, G_SMEM_BYTES);
    cudaFuncSetAttribute(gemm_tf32<true, false>,
                         cudaFuncAttributeMaxDynamicSharedMemorySize, G_SMEM_BYTES);

    const int WN4 = DMODEL * DMODEL / 4;   // 262144
    float* wq = wr;
    float* wk = wr + DMODEL * DMODEL;
    float* wv = wr + 2 * DMODEL * DMODEL;
    float* wo = wr + 3 * DMODEL * DMODEL;

    // 0) pre-round weights + V input to tf32
    round_tf32<<<WN4 / 256, 256>>>(Wq, wq, WN4);
    round_tf32<<<WN4 / 256, 256>>>(Wk, wk, WN4);
    round_tf32<<<WN4 / 256, 256>>>(Wv, wv, WN4);
    round_tf32<<<WN4 / 256, 256>>>(Wo, wo, WN4);
    round_tf32<<<NTOT / 4 / 256, 256>>>(Vin, vr, NTOT / 4);

    // 1) pre-LN on Q and K (tf32-rounded outputs)
    ln_kernel<false><<<MROWS, 256>>>(Q,   pre_g, pre_b, qn, nullptr);
    ln_kernel<false><<<MROWS, 256>>>(Kin, pre_g, pre_b, kn, nullptr);

    // 2) projections (outputs tf32-rounded for flash)
    dim3 gg(DMODEL / 128, MROWS / 128);
    gemm_tf32<false, true><<<gg, 256, G_SMEM_BYTES>>>(qn, wq, qq, nullptr, MROWS, DMODEL, DMODEL);
    gemm_tf32<false, true><<<gg, 256, G_SMEM_BYTES>>>(kn, wk, kk, nullptr, MROWS, DMODEL, DMODEL);
    gemm_tf32<false, true><<<gg, 256, G_SMEM_BYTES>>>(vr, wv, vv, nullptr, MROWS, DMODEL, DMODEL);

    // 3) attention
    flash_tc<<<dim3(SEQ / 128, BATCH * NHEAD), 256, FA_SMEM_BYTES>>>(qq, kk, vv, oo);

    // 4) post-LN: rounded copy (GEMM A) + full copy (residual)
    ln_kernel<true><<<MROWS, 256>>>(oo, ln_g, ln_b, olnR, olnF);

    // 5) output GEMM + gelu residual epilogue (full precision out)
    gemm_tf32<true, false><<<gg, 256, G_SMEM_BYTES>>>(olnR, wo, out, olnF, MROWS, DMODEL, DMODEL);
}